// round 5
// baseline (speedup 1.0000x reference)
#include <cuda_runtime.h>

#define B_ROWS 512
#define S_LEN 16384
#define NTHREADS 1024
#define NWARPS (NTHREADS / 32)   // 32 warps — matches warp width for the 2-level scan
#define TPT 16                   // tokens per thread: 1024 * 16 = 16384

// -------- per-block result slots (plain stores each run; no zeroing needed) ----
__device__ int pC[B_ROWS];   // time-token count per row
__device__ int pS[B_ROWS];   // sum of squared gaps per row
__device__ int pL[B_ROWS];   // voice leap count per row
__device__ int pH[B_ROWS];   // tritone pair count per row
__device__ int pMn[B_ROWS];  // first time-token position per row
__device__ int pMx[B_ROWS];  // last time-token position per row

struct Smem {
    int is64;
    int wT[NWARPS];       // warp-aggregate: last time-token position in warp
    int wN[NWARPS];       // warp-aggregate: last note-token value in warp
    int firstTok[NWARPS]; // first token value of each warp (lane 0's t[0])
    int rC[NWARPS], rS[NWARPS], rL[NWARPS], rH[NWARPS], rMn[NWARPS], rMx[NWARPS];
};

template <bool IS64>
__device__ __forceinline__ void row_impl(const void* __restrict__ in, Smem* sm) {
    const int row = blockIdx.x;
    const int tid = threadIdx.x;
    const int lid = tid & 31;
    const int wid = tid >> 5;
    const unsigned FULL = 0xffffffffu;
    const long long base = (long long)row * S_LEN + (long long)tid * TPT;

    // ---- load 16 tokens (8x LDG.128 for int64 -> MLP 8) ----
    int t[TPT];
    if (IS64) {
        const longlong2* p = (const longlong2*)((const long long*)in + base);
        #pragma unroll
        for (int i = 0; i < TPT / 2; i++) {
            longlong2 v = p[i];
            t[2 * i]     = (int)v.x;
            t[2 * i + 1] = (int)v.y;
        }
    } else {
        const int4* p = (const int4*)((const int*)in + base);
        #pragma unroll
        for (int i = 0; i < TPT / 4; i++) {
            int4 v = p[i];
            t[4 * i] = v.x; t[4 * i + 1] = v.y; t[4 * i + 2] = v.z; t[4 * i + 3] = v.w;
        }
    }

    // ---- thread-local sequential pass ----
    const int pbase = tid * TPT;
    int firstT = -1, lastT = -1, cntT = 0;   // time tokens: positions
    int firstN = -1, lastN = -1;             // note tokens: values
    int sumd2 = 0, leaps = 0, harm = 0;
    int prevPc = 0;
    bool prevNote = false;

    #pragma unroll
    for (int j = 0; j < TPT; j++) {
        int v = t[j];
        int p = pbase + j;
        bool nt = (unsigned)v < 128u;           // note_on token
        bool tm = (unsigned)(v - 256) < 512u;   // time_shift token
        int pc = (int)((unsigned)v % 12u);      // pitch class
        if (tm) {
            if (lastT >= 0) { int d = p - lastT; sumd2 += d * d; }
            else            { firstT = p; }
            lastT = p;
            cntT++;
        }
        if (nt) {
            if (lastN >= 0) { int iv = v - lastN; leaps += (iv > 12) || (iv < -12); }
            else            { firstN = v; }
            lastN = v;
            if (prevNote) {
                int dpc = pc - prevPc;
                harm += (dpc == 6) || (dpc == -6);
            }
        }
        prevNote = nt;
        prevPc = pc;
    }

    // ---- level 1: warp-level "last valid" exclusive scan via ballot ----
    unsigned mT = __ballot_sync(FULL, lastT >= 0);
    unsigned mN = __ballot_sync(FULL, lastN >= 0);
    unsigned below = (1u << lid) - 1u;

    int srcT = 31 - __clz(mT & below);          // -1 if no valid lane below
    int srcN = 31 - __clz(mN & below);
    int exT_w = __shfl_sync(FULL, lastT, srcT & 31);
    int exN_w = __shfl_sync(FULL, lastN, srcN & 31);
    bool hasTw = (mT & below) != 0;
    bool hasNw = (mN & below) != 0;

    // warp inclusive aggregate (value at highest valid lane)
    int aggT = -1, aggN = -1;
    if (mT) aggT = __shfl_sync(FULL, lastT, 31 - __clz(mT));
    if (mN) aggN = __shfl_sync(FULL, lastN, 31 - __clz(mN));

    if (lid == 0) {
        sm->wT[wid] = aggT;
        sm->wN[wid] = aggN;
        sm->firstTok[wid] = t[0];
    }
    __syncthreads();

    // ---- level 2: scan the 32 warp aggregates (one warp-width, every warp) ----
    int vT = sm->wT[lid];
    int vN = sm->wN[lid];
    unsigned mWT = __ballot_sync(FULL, vT >= 0);
    unsigned mWN = __ballot_sync(FULL, vN >= 0);
    unsigned belowW = (1u << wid) - 1u;
    int sW_T = 31 - __clz(mWT & belowW);
    int sW_N = 31 - __clz(mWN & belowW);
    int exWarpT = __shfl_sync(FULL, vT, sW_T & 31);
    int exWarpN = __shfl_sync(FULL, vN, sW_N & 31);
    bool hasWT = (mWT & belowW) != 0;
    bool hasWN = (mWN & belowW) != 0;

    int exT = hasTw ? exT_w : (hasWT ? exWarpT : -1);
    int exN = hasNw ? exN_w : (hasWN ? exWarpN : -1);

    // ---- cross-thread boundary contributions ----
    if (firstT >= 0 && exT >= 0) { int d = firstT - exT; sumd2 += d * d; }
    if (firstN >= 0 && exN >= 0) { int iv = firstN - exN; leaps += (iv > 12) || (iv < -12); }

    // harmony boundary: my last token vs next thread's first token
    int nv = __shfl_down_sync(FULL, t[0], 1);
    if (lid == 31) nv = (wid < NWARPS - 1) ? sm->firstTok[wid + 1] : -1;
    if (tid < NTHREADS - 1 && prevNote && (unsigned)nv < 128u) {
        int dpc = (int)((unsigned)nv % 12u) - prevPc;
        harm += (dpc == 6) || (dpc == -6);
    }

    // ---- block reduction ----
    int mnF = (firstT < 0) ? 0x7fffffff : firstT;
    int mxL = lastT;
    #pragma unroll
    for (int off = 16; off > 0; off >>= 1) {
        cntT  += __shfl_down_sync(FULL, cntT,  off);
        sumd2 += __shfl_down_sync(FULL, sumd2, off);
        leaps += __shfl_down_sync(FULL, leaps, off);
        harm  += __shfl_down_sync(FULL, harm,  off);
        mnF = min(mnF, __shfl_down_sync(FULL, mnF, off));
        mxL = max(mxL, __shfl_down_sync(FULL, mxL, off));
    }
    if (lid == 0) {
        sm->rC[wid] = cntT;  sm->rS[wid] = sumd2; sm->rL[wid] = leaps;
        sm->rH[wid] = harm;  sm->rMn[wid] = mnF;  sm->rMx[wid] = mxL;
    }
    __syncthreads();
    if (wid == 0) {
        cntT  = sm->rC[lid];  sumd2 = sm->rS[lid]; leaps = sm->rL[lid];
        harm  = sm->rH[lid];  mnF   = sm->rMn[lid]; mxL  = sm->rMx[lid];
        #pragma unroll
        for (int off = 16; off > 0; off >>= 1) {
            cntT  += __shfl_down_sync(FULL, cntT,  off);
            sumd2 += __shfl_down_sync(FULL, sumd2, off);
            leaps += __shfl_down_sync(FULL, leaps, off);
            harm  += __shfl_down_sync(FULL, harm,  off);
            mnF = min(mnF, __shfl_down_sync(FULL, mnF, off));
            mxL = max(mxL, __shfl_down_sync(FULL, mxL, off));
        }
        if (lid == 0) {
            pC[row] = cntT;  pS[row] = sumd2; pL[row] = leaps;
            pH[row] = harm;  pMn[row] = mnF;  pMx[row] = mxL;
        }
    }
}

__global__ void __launch_bounds__(NTHREADS, 1)
row_kernel(const void* __restrict__ in) {
    __shared__ Smem sm;
    // Per-block dtype detection: 2 independent 16B loads of the first 4 words.
    // int64 -> all 4 values in [0, 1024); int32 -> an 8B word packs two tokens
    // and is >= 2^32 unless the odd token is 0 (fixed dataset: never all-zero).
    if (threadIdx.x == 0) {
        const longlong2* p = (const longlong2*)in;
        longlong2 a = p[0];
        longlong2 b = p[1];
        int ok = (a.x >= 0 && a.x < 1024) && (a.y >= 0 && a.y < 1024) &&
                 (b.x >= 0 && b.x < 1024) && (b.y >= 0 && b.y < 1024);
        sm.is64 = ok;
    }
    __syncthreads();
    if (sm.is64) row_impl<true>(in, &sm);
    else         row_impl<false>(in, &sm);
}

// -------- parallel finalize: reduce 512 row slots, compute the 4 outputs ------
__global__ void __launch_bounds__(512)
finalize_kernel(float* __restrict__ out) {
    __shared__ int rN[16], rD[16], rS[16], rH[16], rL[16];
    const unsigned FULL = 0xffffffffu;
    int tid = threadIdx.x;
    int lid = tid & 31, wid = tid >> 5;

    int cnt = pC[tid];
    int n_row    = (cnt > 1)  ? (cnt - 1)          : 0;
    int sumd_row = (cnt >= 2) ? (pMx[tid] - pMn[tid]) : 0;
    int s2 = pS[tid], hm = pH[tid], lp = pL[tid];

    #pragma unroll
    for (int off = 16; off > 0; off >>= 1) {
        n_row    += __shfl_down_sync(FULL, n_row,    off);
        sumd_row += __shfl_down_sync(FULL, sumd_row, off);
        s2       += __shfl_down_sync(FULL, s2,       off);
        hm       += __shfl_down_sync(FULL, hm,       off);
        lp       += __shfl_down_sync(FULL, lp,       off);
    }
    if (lid == 0) { rN[wid] = n_row; rD[wid] = sumd_row; rS[wid] = s2; rH[wid] = hm; rL[wid] = lp; }
    __syncthreads();
    if (wid == 0) {
        n_row    = (lid < 16) ? rN[lid] : 0;
        sumd_row = (lid < 16) ? rD[lid] : 0;
        s2       = (lid < 16) ? rS[lid] : 0;
        hm       = (lid < 16) ? rH[lid] : 0;
        lp       = (lid < 16) ? rL[lid] : 0;
        #pragma unroll
        for (int off = 8; off > 0; off >>= 1) {
            n_row    += __shfl_down_sync(FULL, n_row,    off);
            sumd_row += __shfl_down_sync(FULL, sumd_row, off);
            s2       += __shfl_down_sync(FULL, s2,       off);
            hm       += __shfl_down_sync(FULL, hm,       off);
            lp       += __shfl_down_sync(FULL, lp,       off);
        }
        if (lid == 0) {
            double N     = (double)n_row;
            double sumd  = (double)sumd_row;
            double sumd2 = (double)s2;
            double mean  = sumd / (N > 1.0 ? N : 1.0);
            double ss    = sumd2 - 2.0 * mean * sumd + N * mean * mean;
            double var   = (N > 1.0) ? (ss / (N - 1.0)) : 0.0;
            float rhythm  = (float)(var * 0.01);
            float harmony = (float)(0.1 * (double)hm / (double)((long long)B_ROWS * S_LEN));
            float voice   = (float)((double)lp / (double)B_ROWS);
            float total   = rhythm + harmony + 0.5f * voice;
            out[0] = rhythm; out[1] = harmony; out[2] = voice; out[3] = total;
        }
    }
}

extern "C" void kernel_launch(void* const* d_in, const int* in_sizes, int n_in,
                              void* d_out, int out_size) {
    const void* in = d_in[0];
    row_kernel<<<B_ROWS, NTHREADS>>>(in);
    finalize_kernel<<<1, 512>>>((float*)d_out);
}